// round 11
// baseline (speedup 1.0000x reference)
#include <cuda_runtime.h>
#include <cstdint>
#include <math.h>

#define DEV_INLINE __device__ __forceinline__

constexpr int B_   = 32;
constexpr int H_   = 32;
constexpr int HKV_ = 8;
constexpr int D_   = 128;
constexpr int G_   = 4;      // H_/HKV_
constexpr int N_   = 4096;
constexpr int NB_  = 256;    // 16-token paged blocks per sequence
constexpr int SPLIT = 16;    // token splits per (b,kh)
constexpr int WARPS = 4;     // warps per CTA (128 threads)
constexpr int THREADS = WARPS * 32;
constexpr int TPS = N_ / SPLIT;     // 256 tokens per CTA
constexpr int TPW = TPS / WARPS;    // 64 tokens per warp
constexpr int NSTG = TPW / 2;       // 32 warp-stages of 2 tokens
constexpr int DEPTH = 4;            // warp-private ring slots (32 KB total)
constexpr int LOOKAHEAD = 3;        // stages in flight per warp
constexpr int SLOT_F = 512;         // floats per slot: 2 tok x (128 K + 128 V)
constexpr float SCALE_ = 0.08838834764831845f;
constexpr float LOG2E  = 1.4426950408889634f;
constexpr float SCALE_L2E = SCALE_ * LOG2E;     // qr prescale (exp2 domain)
constexpr float MFIX   = 16.0f;                 // fixed softmax max
constexpr float C16    = MFIX * LOG2E;          // subtract in exp2 domain

// Partial scratch (allocation-free __device__ globals)
// layout: [b][kh][split][g] -> acc[128], (M,L)
__device__ float g_pacc[(size_t)B_ * HKV_ * SPLIT * G_ * D_];
__device__ float g_pml[(size_t)B_ * HKV_ * SPLIT * G_ * 2];

DEV_INLINE void cp_async16(unsigned int smem_addr, const void* gptr) {
    asm volatile("cp.async.cg.shared.global [%0], [%1], 16;\n"
                 :: "r"(smem_addr), "l"(gptr));
}
DEV_INLINE void cp_commit() { asm volatile("cp.async.commit_group;\n"); }
template <int NN> DEV_INLINE void cp_wait() {
    asm volatile("cp.async.wait_group %0;\n" :: "n"(NN));
}

__global__ __launch_bounds__(THREADS, 7)
void attn_main(const float* __restrict__ Q,
               const float* __restrict__ Kc,
               const float* __restrict__ Vc,
               const float* __restrict__ cosp,
               const float* __restrict__ sinp,
               const int* __restrict__ bt)
{
    const int b  = blockIdx.z;
    const int kh = blockIdx.y;
    const int sp = blockIdx.x;
    const int tid = threadIdx.x;
    const int w   = tid >> 5;
    const int lid = tid & 31;
    const int gsel = (lid >> 2) & 3;    // group this lane finishes in the reduction

    // 32 KB static: 4 warp-private rings of DEPTH x SLOT_F floats
    __shared__ __align__(16) float ssm[WARPS * DEPTH * SLOT_F];
    float* ring = ssm + w * (DEPTH * SLOT_F);

    // Lane owns d-chunk: d = lid*4 + j (full-warp spread -> 2 LDS/token)
    // qr[g][j]: RoPE'd Q, pre-scaled by SCALE*log2(e)
    float qr[G_][4];
    {
        const float* cb = cosp + (size_t)b * D_;
        const float* sb = sinp + (size_t)b * D_;
        #pragma unroll
        for (int g = 0; g < G_; g++) {
            const float* qb = Q + ((size_t)b * H_ + g * HKV_ + kh) * D_;
            #pragma unroll
            for (int j = 0; j < 4; j++) {
                const int d = lid * 4 + j;
                const float sign = (d < 64) ? -1.f : 1.f;
                qr[g][j] = (qb[d] * cb[d] + sign * qb[d ^ 64] * sb[d]) * SCALE_L2E;
            }
        }
    }

    // 4 paged blocks per warp; precompute flat offsets
    const int* btb = bt + (size_t)b * NB_ + sp * (TPS / 16) + w * (TPW / 16);
    size_t boff[4];
    #pragma unroll
    for (int i = 0; i < 4; i++)
        boff[i] = (size_t)__ldg(btb + i) * 16384 + (size_t)kh * 2048;

    auto issue = [&](int st) {
        const size_t o = boff[st >> 3] + (size_t)((st * 2) & 15) * 128;
        const float* gK = Kc + o;
        const float* gV = Vc + o;
        unsigned int s = (unsigned int)__cvta_generic_to_shared(ring + (st % DEPTH) * SLOT_F);
        cp_async16(s +    0 + lid * 16, gK + lid * 4);
        cp_async16(s +  512 + lid * 16, gV + lid * 4);
        cp_async16(s + 1024 + lid * 16, gK + 128 + lid * 4);
        cp_async16(s + 1536 + lid * 16, gV + 128 + lid * 4);
    };

    #pragma unroll
    for (int s = 0; s < LOOKAHEAD; s++) { issue(s); cp_commit(); }

    float l_acc = 0.f;             // per-lane: TRUE l for group gsel
    float acc[G_][4];
    #pragma unroll
    for (int g = 0; g < G_; g++)
        #pragma unroll
        for (int j = 0; j < 4; j++) acc[g][j] = 0.f;

    const int tg0 = sp * TPS + w * TPW;

    for (int st = 0; st < NSTG; st++) {
        cp_wait<LOOKAHEAD - 1>();           // stage st arrived (own warp's groups)
        const float* slot = ring + (st % DEPTH) * SLOT_F;
        const int njj = min(2, (N_ - 1) - (tg0 + st * 2));  // exclude current token

        #pragma unroll
        for (int jj = 0; jj < 2; jj++) {
            if (jj < njj) {
                // one K row + one V row, 16B per lane, conflict-free
                const float4 kv = reinterpret_cast<const float4*>(slot + jj * 256)[lid];
                const float4 vv = reinterpret_cast<const float4*>(slot + jj * 256 + 128)[lid];

                float s0 = qr[0][0]*kv.x + qr[0][1]*kv.y + qr[0][2]*kv.z + qr[0][3]*kv.w;
                float s1 = qr[1][0]*kv.x + qr[1][1]*kv.y + qr[1][2]*kv.z + qr[1][3]*kv.w;
                float s2 = qr[2][0]*kv.x + qr[2][1]*kv.y + qr[2][2]*kv.z + qr[2][3]*kv.w;
                float s3 = qr[3][0]*kv.x + qr[3][1]*kv.y + qr[3][2]*kv.z + qr[3][3]*kv.w;

                // butterfly over bits 4,3,2: partial per class (lid&3)
                #pragma unroll
                for (int o = 16; o >= 4; o >>= 1) {
                    s0 += __shfl_xor_sync(0xffffffffu, s0, o);
                    s1 += __shfl_xor_sync(0xffffffffu, s1, o);
                    s2 += __shfl_xor_sync(0xffffffffu, s2, o);
                    s3 += __shfl_xor_sync(0xffffffffu, s3, o);
                }
                // lane picks its group's class-partial, finishes over bits 0,1
                float val = (gsel == 0) ? s0 : (gsel == 1) ? s1 : (gsel == 2) ? s2 : s3;
                val += __shfl_xor_sync(0xffffffffu, val, 1);
                val += __shfl_xor_sync(0xffffffffu, val, 2);
                // val = FULL score for group gsel (uniform in bits 0,1,4)

                const float pv = exp2f(val - C16);      // = e^(s_g - 16)
                l_acc += pv;                            // true l (no cross-lane sum)

                const float p0 = __shfl_sync(0xffffffffu, pv, 0);
                const float p1 = __shfl_sync(0xffffffffu, pv, 4);
                const float p2 = __shfl_sync(0xffffffffu, pv, 8);
                const float p3 = __shfl_sync(0xffffffffu, pv, 12);

                acc[0][0]+=p0*vv.x; acc[0][1]+=p0*vv.y; acc[0][2]+=p0*vv.z; acc[0][3]+=p0*vv.w;
                acc[1][0]+=p1*vv.x; acc[1][1]+=p1*vv.y; acc[1][2]+=p1*vv.z; acc[1][3]+=p1*vv.w;
                acc[2][0]+=p2*vv.x; acc[2][1]+=p2*vv.y; acc[2][2]+=p2*vv.z; acc[2][3]+=p2*vv.w;
                acc[3][0]+=p3*vv.x; acc[3][1]+=p3*vv.y; acc[3][2]+=p3*vv.z; acc[3][3]+=p3*vv.w;
            }
        }

        if (st + LOOKAHEAD < NSTG) issue(st + LOOKAHEAD);  // own-warp refill, no barrier
        cp_commit();   // possibly-empty group keeps wait counting sound
    }

    cp_wait<0>();
    __syncthreads();

    // CTA-level combine of 4 warp partials (all share M = MFIX -> plain sums)
    float* s_acc = ssm;                 // [WARPS][G_][D_] = 2048 floats
    float* s_l   = ssm + WARPS * G_ * D_;   // [WARPS][G_]

    #pragma unroll
    for (int g = 0; g < G_; g++) {
        float4* dst = reinterpret_cast<float4*>(s_acc + (w * G_ + g) * D_);
        dst[lid] = make_float4(acc[g][0], acc[g][1], acc[g][2], acc[g][3]);
    }
    if (lid < 16 && (lid & 3) == 0)     // lanes 0,4,8,12 hold true l for g=0..3
        s_l[w * G_ + gsel] = l_acc;
    __syncthreads();

    for (int idx = tid; idx < G_ * D_; idx += THREADS) {
        const int gg = idx >> 7;
        const int d  = idx & 127;
        float A = 0.f, L = 0.f;
        #pragma unroll
        for (int ww = 0; ww < WARPS; ww++) {
            A += s_acc[(ww * G_ + gg) * D_ + d];
            L += s_l[ww * G_ + gg];
        }
        const size_t o = (((size_t)b * HKV_ + kh) * SPLIT + sp) * G_ + gg;
        g_pacc[o * D_ + d] = A;
        if (d == 0) { g_pml[o * 2] = MFIX; g_pml[o * 2 + 1] = L; }
    }
}

__global__ __launch_bounds__(128)
void attn_combine(const float* __restrict__ Q,
                  const float* __restrict__ K,
                  const float* __restrict__ V,
                  const float* __restrict__ cosp,
                  const float* __restrict__ sinp,
                  float* __restrict__ out)
{
    const int h = blockIdx.x;
    const int b = blockIdx.y;
    const int g  = h >> 3;
    const int kh = h & 7;
    const int d    = threadIdx.x;     // 0..127
    const int lane = d & 31;
    const int wrp  = d >> 5;

    const float cv = cosp[(size_t)b * D_ + d];
    const float sv = sinp[(size_t)b * D_ + d];
    const float sign = (d < 64) ? -1.f : 1.f;
    const float* qb = Q + ((size_t)b * H_ + h) * D_;
    const float* kb = K + ((size_t)b * HKV_ + kh) * D_;
    const float qrv = qb[d] * cv + sign * qb[d ^ 64] * sv;
    const float krv = kb[d] * cv + sign * kb[d ^ 64] * sv;

    __shared__ float red[4];
    float part = qrv * krv;
    #pragma unroll
    for (int o = 16; o; o >>= 1) part += __shfl_xor_sync(0xffffffffu, part, o);
    if (lane == 0) red[wrp] = part;
    __syncthreads();
    const float s_cur = (red[0] + red[1] + red[2] + red[3]) * SCALE_;

    const size_t base = ((size_t)b * HKV_ + kh) * SPLIT * G_ + g;
    const float M  = fmaxf(s_cur, MFIX);         // all split partials share M = MFIX
    const float ec = __expf(s_cur - M);
    const float cf = __expf(MFIX - M);
    float L  = ec;
    float o_ = ec * V[((size_t)b * HKV_ + kh) * D_ + d];   // current token: raw V
    #pragma unroll
    for (int i = 0; i < SPLIT; i++) {
        const size_t pi = base + (size_t)i * G_;
        L  += g_pml[pi * 2 + 1] * cf;
        o_ += g_pacc[pi * D_ + d] * cf;
    }
    out[((size_t)b * H_ + h) * D_ + d] = o_ / L;
}

extern "C" void kernel_launch(void* const* d_in, const int* in_sizes, int n_in,
                              void* d_out, int out_size)
{
    const float* Q    = (const float*)d_in[0];
    const float* K    = (const float*)d_in[1];
    const float* V    = (const float*)d_in[2];
    const float* Kc   = (const float*)d_in[3];
    const float* Vc   = (const float*)d_in[4];
    const float* cosp = (const float*)d_in[5];
    const float* sinp = (const float*)d_in[6];
    const int*   bt   = (const int*)d_in[7];
    float* out = (float*)d_out;

    dim3 grid_main(SPLIT, HKV_, B_);
    attn_main<<<grid_main, THREADS>>>(Q, Kc, Vc, cosp, sinp, bt);

    dim3 grid_comb(H_, B_);
    attn_combine<<<grid_comb, 128>>>(Q, K, V, cosp, sinp, out);
}

// round 12
// speedup vs baseline: 1.0246x; 1.0246x over previous
#include <cuda_runtime.h>
#include <cstdint>
#include <math.h>

#define DEV_INLINE __device__ __forceinline__

constexpr int B_   = 32;
constexpr int H_   = 32;
constexpr int HKV_ = 8;
constexpr int D_   = 128;
constexpr int G_   = 4;      // H_/HKV_
constexpr int N_   = 4096;
constexpr int NB_  = 256;    // 16-token paged blocks per sequence
constexpr int WARPS = 8;
constexpr int THREADS = 256;
constexpr int DEPTH = 4;            // warp-private ring slots (64 KB total)
constexpr int LOOKAHEAD = 3;        // stages in flight per warp
constexpr int SLOT_F = 512;         // floats per slot: 2 tok x (128 K + 128 V)

// Two-class decomposition: 222 pairs x 8 big splits (32 blocks) = 1776 = 4*444 CTAs
// (exactly 4 full waves at occ 3), then 34 pairs x 32 small splits (8 blocks) = 1088.
constexpr int A_PAIRS = 222;
constexpr int A_JOBS  = A_PAIRS * 8;          // 1776
constexpr int GRID_MAIN = A_JOBS + (B_ * HKV_ - A_PAIRS) * 32;  // 1776 + 1088 = 2864
constexpr int SLOTS_PP = 32;                  // scratch slots per pair (A uses 8)

constexpr float SCALE_ = 0.08838834764831845f;
constexpr float LOG2E  = 1.4426950408889634f;
constexpr float SCALE_L2E = SCALE_ * LOG2E;   // qr prescale (exp2 domain)
constexpr float MFIX   = 16.0f;               // fixed softmax max
constexpr float C16    = MFIX * LOG2E;        // subtract in exp2 domain

// Partial scratch (allocation-free __device__ globals)
// layout: [pair][slot][g][d] and [pair][slot][g]
__device__ float g_pacc[(size_t)B_ * HKV_ * SLOTS_PP * G_ * D_];   // 16.8 MB
__device__ float g_pl[(size_t)B_ * HKV_ * SLOTS_PP * G_];

DEV_INLINE void cp_async16(unsigned int smem_addr, const void* gptr) {
    asm volatile("cp.async.cg.shared.global [%0], [%1], 16;\n"
                 :: "r"(smem_addr), "l"(gptr));
}
DEV_INLINE void cp_commit() { asm volatile("cp.async.commit_group;\n"); }
template <int NN> DEV_INLINE void cp_wait() {
    asm volatile("cp.async.wait_group %0;\n" :: "n"(NN));
}

__global__ __launch_bounds__(THREADS, 3)
void attn_main(const float* __restrict__ Q,
               const float* __restrict__ Kc,
               const float* __restrict__ Vc,
               const float* __restrict__ cosp,
               const float* __restrict__ sinp,
               const int* __restrict__ bt)
{
    const int c   = blockIdx.x;
    const int tid = threadIdx.x;
    const int w   = tid >> 5;
    const int lid = tid & 31;
    const int gsel = (lid >> 2) & 3;    // group this lane finishes in the reduction

    // decode two-class work assignment
    int p, sp, nbw;          // pair, split, blocks-per-warp
    if (c < A_JOBS) { p = c >> 3;               sp = c & 7;  nbw = 4; }
    else            { const int cc = c - A_JOBS; p = A_PAIRS + (cc >> 5); sp = cc & 31; nbw = 1; }
    const int b  = p >> 3;
    const int kh = p & 7;
    const int block0_w = (nbw == 4) ? (sp * 32 + w * 4) : (sp * 8 + w);
    const int NSTG_rt  = nbw * 8;       // stages of 2 tokens: 32 (A) or 8 (B)

    // 64 KB static: 8 warp-private rings of DEPTH x SLOT_F floats
    __shared__ __align__(16) float ssm[WARPS * DEPTH * SLOT_F];
    float* ring = ssm + w * (DEPTH * SLOT_F);

    // Lane owns d-chunk: d = lid*4 + j (full-warp spread -> 2 LDS/token)
    float qr[G_][4];
    {
        const float* cb = cosp + (size_t)b * D_;
        const float* sb = sinp + (size_t)b * D_;
        #pragma unroll
        for (int g = 0; g < G_; g++) {
            const float* qb = Q + ((size_t)b * H_ + g * HKV_ + kh) * D_;
            #pragma unroll
            for (int j = 0; j < 4; j++) {
                const int d = lid * 4 + j;
                const float sign = (d < 64) ? -1.f : 1.f;
                qr[g][j] = (qb[d] * cb[d] + sign * qb[d ^ 64] * sb[d]) * SCALE_L2E;
            }
        }
    }

    // paged-block offsets for this warp (guard OOB for class B)
    const int* btb = bt + (size_t)b * NB_ + block0_w;
    size_t boff[4];
    #pragma unroll
    for (int i = 0; i < 4; i++) {
        const int idx = (i < nbw) ? i : 0;
        boff[i] = (size_t)__ldg(btb + idx) * 16384 + (size_t)kh * 2048;
    }

    auto issue = [&](int st) {
        const size_t o = boff[st >> 3] + (size_t)((st * 2) & 15) * 128;
        const float* gK = Kc + o;
        const float* gV = Vc + o;
        unsigned int s = (unsigned int)__cvta_generic_to_shared(ring + (st % DEPTH) * SLOT_F);
        cp_async16(s +    0 + lid * 16, gK + lid * 4);
        cp_async16(s +  512 + lid * 16, gV + lid * 4);
        cp_async16(s + 1024 + lid * 16, gK + 128 + lid * 4);
        cp_async16(s + 1536 + lid * 16, gV + 128 + lid * 4);
    };

    #pragma unroll
    for (int s = 0; s < LOOKAHEAD; s++) { issue(s); cp_commit(); }

    float l_acc = 0.f;             // per-lane: TRUE l for group gsel
    float acc[G_][4];
    #pragma unroll
    for (int g = 0; g < G_; g++)
        #pragma unroll
        for (int j = 0; j < 4; j++) acc[g][j] = 0.f;

    const int tg0 = block0_w * 16;  // global token index of warp's first token

    for (int st = 0; st < NSTG_rt; st++) {
        cp_wait<LOOKAHEAD - 1>();           // stage st arrived (own warp's groups)
        const float* slot = ring + (st % DEPTH) * SLOT_F;
        const int njj = min(2, (N_ - 1) - (tg0 + st * 2));  // exclude current token

        #pragma unroll
        for (int jj = 0; jj < 2; jj++) {
            if (jj < njj) {
                // one K row + one V row, 16B per lane, conflict-free
                const float4 kv = reinterpret_cast<const float4*>(slot + jj * 256)[lid];
                const float4 vv = reinterpret_cast<const float4*>(slot + jj * 256 + 128)[lid];

                float s0 = qr[0][0]*kv.x + qr[0][1]*kv.y + qr[0][2]*kv.z + qr[0][3]*kv.w;
                float s1 = qr[1][0]*kv.x + qr[1][1]*kv.y + qr[1][2]*kv.z + qr[1][3]*kv.w;
                float s2 = qr[2][0]*kv.x + qr[2][1]*kv.y + qr[2][2]*kv.z + qr[2][3]*kv.w;
                float s3 = qr[3][0]*kv.x + qr[3][1]*kv.y + qr[3][2]*kv.z + qr[3][3]*kv.w;

                // butterfly over bits 4,3,2: partial per class (lid&3)
                #pragma unroll
                for (int o = 16; o >= 4; o >>= 1) {
                    s0 += __shfl_xor_sync(0xffffffffu, s0, o);
                    s1 += __shfl_xor_sync(0xffffffffu, s1, o);
                    s2 += __shfl_xor_sync(0xffffffffu, s2, o);
                    s3 += __shfl_xor_sync(0xffffffffu, s3, o);
                }
                // lane picks its group's class-partial, finishes over bits 0,1
                float val = (gsel == 0) ? s0 : (gsel == 1) ? s1 : (gsel == 2) ? s2 : s3;
                val += __shfl_xor_sync(0xffffffffu, val, 1);
                val += __shfl_xor_sync(0xffffffffu, val, 2);
                // val = FULL score for group gsel (uniform in bits 0,1,4)

                const float pv = exp2f(val - C16);      // = e^(s_g - 16)
                l_acc += pv;                            // true l (no cross-lane sum)

                const float p0 = __shfl_sync(0xffffffffu, pv, 0);
                const float p1 = __shfl_sync(0xffffffffu, pv, 4);
                const float p2 = __shfl_sync(0xffffffffu, pv, 8);
                const float p3 = __shfl_sync(0xffffffffu, pv, 12);

                acc[0][0]+=p0*vv.x; acc[0][1]+=p0*vv.y; acc[0][2]+=p0*vv.z; acc[0][3]+=p0*vv.w;
                acc[1][0]+=p1*vv.x; acc[1][1]+=p1*vv.y; acc[1][2]+=p1*vv.z; acc[1][3]+=p1*vv.w;
                acc[2][0]+=p2*vv.x; acc[2][1]+=p2*vv.y; acc[2][2]+=p2*vv.z; acc[2][3]+=p2*vv.w;
                acc[3][0]+=p3*vv.x; acc[3][1]+=p3*vv.y; acc[3][2]+=p3*vv.z; acc[3][3]+=p3*vv.w;
            }
        }

        if (st + LOOKAHEAD < NSTG_rt) issue(st + LOOKAHEAD);  // own-warp refill
        cp_commit();   // possibly-empty group keeps wait counting sound
    }

    cp_wait<0>();
    __syncthreads();

    // CTA-level combine of 8 warp partials (all share M = MFIX -> plain sums)
    float* s_acc = ssm;                 // [WARPS][G_][D_] = 4096 floats
    float* s_l   = ssm + WARPS * G_ * D_;   // [WARPS][G_]

    #pragma unroll
    for (int g = 0; g < G_; g++) {
        float4* dst = reinterpret_cast<float4*>(s_acc + (w * G_ + g) * D_);
        dst[lid] = make_float4(acc[g][0], acc[g][1], acc[g][2], acc[g][3]);
    }
    if (lid < 16 && (lid & 3) == 0)     // lanes 0,4,8,12 hold true l for g=0..3
        s_l[w * G_ + gsel] = l_acc;
    __syncthreads();

    const size_t S = (size_t)p * SLOTS_PP + sp;     // this CTA's scratch slot
    for (int idx = tid; idx < G_ * D_; idx += THREADS) {
        const int gg = idx >> 7;
        const int d  = idx & 127;
        float A = 0.f, L = 0.f;
        #pragma unroll
        for (int ww = 0; ww < WARPS; ww++) {
            A += s_acc[(ww * G_ + gg) * D_ + d];
            L += s_l[ww * G_ + gg];
        }
        g_pacc[(S * G_ + gg) * D_ + d] = A;
        if (d == 0) g_pl[S * G_ + gg] = L;
    }
}

__global__ __launch_bounds__(128)
void attn_combine(const float* __restrict__ Q,
                  const float* __restrict__ K,
                  const float* __restrict__ V,
                  const float* __restrict__ cosp,
                  const float* __restrict__ sinp,
                  float* __restrict__ out)
{
    const int h = blockIdx.x;
    const int b = blockIdx.y;
    const int g  = h >> 3;
    const int kh = h & 7;
    const int d    = threadIdx.x;     // 0..127
    const int lane = d & 31;
    const int wrp  = d >> 5;

    const float cv = cosp[(size_t)b * D_ + d];
    const float sv = sinp[(size_t)b * D_ + d];
    const float sign = (d < 64) ? -1.f : 1.f;
    const float* qb = Q + ((size_t)b * H_ + h) * D_;
    const float* kb = K + ((size_t)b * HKV_ + kh) * D_;
    const float qrv = qb[d] * cv + sign * qb[d ^ 64] * sv;
    const float krv = kb[d] * cv + sign * kb[d ^ 64] * sv;

    __shared__ float red[4];
    float part = qrv * krv;
    #pragma unroll
    for (int o = 16; o; o >>= 1) part += __shfl_xor_sync(0xffffffffu, part, o);
    if (lane == 0) red[wrp] = part;
    __syncthreads();
    const float s_cur = (red[0] + red[1] + red[2] + red[3]) * SCALE_;

    const int p = b * HKV_ + kh;
    const int nsp = (p < A_PAIRS) ? 8 : SLOTS_PP;   // slots written for this pair
    const size_t base = (size_t)p * SLOTS_PP;

    const float M  = fmaxf(s_cur, MFIX);         // all split partials share M = MFIX
    const float ec = __expf(s_cur - M);
    const float cf = __expf(MFIX - M);
    float L  = ec;
    float o_ = ec * V[((size_t)b * HKV_ + kh) * D_ + d];   // current token: raw V
    #pragma unroll 8
    for (int i = 0; i < nsp; i++) {
        const size_t S = base + i;
        L  += g_pl[S * G_ + g] * cf;
        o_ += g_pacc[(S * G_ + g) * D_ + d] * cf;
    }
    out[((size_t)b * H_ + h) * D_ + d] = o_ / L;
}

extern "C" void kernel_launch(void* const* d_in, const int* in_sizes, int n_in,
                              void* d_out, int out_size)
{
    const float* Q    = (const float*)d_in[0];
    const float* K    = (const float*)d_in[1];
    const float* V    = (const float*)d_in[2];
    const float* Kc   = (const float*)d_in[3];
    const float* Vc   = (const float*)d_in[4];
    const float* cosp = (const float*)d_in[5];
    const float* sinp = (const float*)d_in[6];
    const int*   bt   = (const int*)d_in[7];
    float* out = (float*)d_out;

    attn_main<<<GRID_MAIN, THREADS>>>(Q, Kc, Vc, cosp, sinp, bt);

    dim3 grid_comb(H_, B_);
    attn_combine<<<grid_comb, 128>>>(Q, K, V, cosp, sinp, out);
}

// round 14
// speedup vs baseline: 1.0250x; 1.0004x over previous
#include <cuda_runtime.h>
#include <cstdint>
#include <math.h>

#define DEV_INLINE __device__ __forceinline__

constexpr int B_   = 32;
constexpr int H_   = 32;
constexpr int HKV_ = 8;
constexpr int D_   = 128;
constexpr int G_   = 4;      // H_/HKV_
constexpr int N_   = 4096;
constexpr int NB_  = 256;    // 16-token paged blocks per sequence
constexpr int WARPS = 8;
constexpr int THREADS = 256;
constexpr int DEPTH = 4;            // warp-private ring slots (64 KB total)
constexpr int LOOKAHEAD = 3;        // stages in flight per warp
constexpr int SLOT_F = 512;         // floats per slot: 2 tok x (128 K + 128 V)

// Two-class decomposition (CLC work-steals after wave 1, so alignment is soft):
// 242 pairs x 8 big splits (32 blocks) = 1936 CTAs, then 14 pairs x 32 small
// splits (8 blocks) = 448 CTAs to smooth the tail (~= one concurrency fill).
constexpr int A_PAIRS = 242;
constexpr int A_JOBS  = A_PAIRS * 8;          // 1936
constexpr int GRID_MAIN = A_JOBS + (B_ * HKV_ - A_PAIRS) * 32;  // 1936 + 448 = 2384
constexpr int SLOTS_PP = 32;                  // scratch slots per pair (A uses 8)

constexpr float SCALE_ = 0.08838834764831845f;
constexpr float LOG2E  = 1.4426950408889634f;
constexpr float SCALE_L2E = SCALE_ * LOG2E;   // qr prescale (exp2 domain)
constexpr float MFIX   = 16.0f;               // fixed softmax max
constexpr float C16    = MFIX * LOG2E;        // subtract in exp2 domain

// Partial scratch (allocation-free __device__ globals)
// layout: [pair][slot][g][d] and [pair][slot][g]
__device__ float g_pacc[(size_t)B_ * HKV_ * SLOTS_PP * G_ * D_];   // 16.8 MB
__device__ float g_pl[(size_t)B_ * HKV_ * SLOTS_PP * G_];

DEV_INLINE void cp_async16(unsigned int smem_addr, const void* gptr) {
    asm volatile("cp.async.cg.shared.global [%0], [%1], 16;\n"
                 :: "r"(smem_addr), "l"(gptr));
}
DEV_INLINE void cp_commit() { asm volatile("cp.async.commit_group;\n"); }
template <int NN> DEV_INLINE void cp_wait() {
    asm volatile("cp.async.wait_group %0;\n" :: "n"(NN));
}

__global__ __launch_bounds__(THREADS, 3)
void attn_main(const float* __restrict__ Q,
               const float* __restrict__ Kc,
               const float* __restrict__ Vc,
               const float* __restrict__ cosp,
               const float* __restrict__ sinp,
               const int* __restrict__ bt)
{
    const int c   = blockIdx.x;
    const int tid = threadIdx.x;
    const int w   = tid >> 5;
    const int lid = tid & 31;
    const int gsel = (lid >> 2) & 3;    // group this lane finishes in the reduction

    // decode two-class work assignment
    int p, sp, nbw;          // pair, split, blocks-per-warp
    if (c < A_JOBS) { p = c >> 3;               sp = c & 7;  nbw = 4; }
    else            { const int cc = c - A_JOBS; p = A_PAIRS + (cc >> 5); sp = cc & 31; nbw = 1; }
    const int b  = p >> 3;
    const int kh = p & 7;
    const int block0_w = (nbw == 4) ? (sp * 32 + w * 4) : (sp * 8 + w);
    const int NSTG_rt  = nbw * 8;       // stages of 2 tokens: 32 (A) or 8 (B)

    // 64 KB static: 8 warp-private rings of DEPTH x SLOT_F floats
    __shared__ __align__(16) float ssm[WARPS * DEPTH * SLOT_F];
    float* ring = ssm + w * (DEPTH * SLOT_F);

    // Lane owns d-chunk: d = lid*4 + j (full-warp spread -> 2 LDS/token)
    float qr[G_][4];
    {
        const float* cb = cosp + (size_t)b * D_;
        const float* sb = sinp + (size_t)b * D_;
        #pragma unroll
        for (int g = 0; g < G_; g++) {
            const float* qb = Q + ((size_t)b * H_ + g * HKV_ + kh) * D_;
            #pragma unroll
            for (int j = 0; j < 4; j++) {
                const int d = lid * 4 + j;
                const float sign = (d < 64) ? -1.f : 1.f;
                qr[g][j] = (qb[d] * cb[d] + sign * qb[d ^ 64] * sb[d]) * SCALE_L2E;
            }
        }
    }

    // paged-block offsets for this warp (guard OOB for class B)
    const int* btb = bt + (size_t)b * NB_ + block0_w;
    size_t boff[4];
    #pragma unroll
    for (int i = 0; i < 4; i++) {
        const int idx = (i < nbw) ? i : 0;
        boff[i] = (size_t)__ldg(btb + idx) * 16384 + (size_t)kh * 2048;
    }

    auto issue = [&](int st) {
        const size_t o = boff[st >> 3] + (size_t)((st * 2) & 15) * 128;
        const float* gK = Kc + o;
        const float* gV = Vc + o;
        unsigned int s = (unsigned int)__cvta_generic_to_shared(ring + (st % DEPTH) * SLOT_F);
        cp_async16(s +    0 + lid * 16, gK + lid * 4);
        cp_async16(s +  512 + lid * 16, gV + lid * 4);
        cp_async16(s + 1024 + lid * 16, gK + 128 + lid * 4);
        cp_async16(s + 1536 + lid * 16, gV + 128 + lid * 4);
    };

    #pragma unroll
    for (int s = 0; s < LOOKAHEAD; s++) { issue(s); cp_commit(); }

    float l_acc = 0.f;             // per-lane: TRUE l for group gsel
    float acc[G_][4];
    #pragma unroll
    for (int g = 0; g < G_; g++)
        #pragma unroll
        for (int j = 0; j < 4; j++) acc[g][j] = 0.f;

    const int tg0 = block0_w * 16;  // global token index of warp's first token

    for (int st = 0; st < NSTG_rt; st++) {
        cp_wait<LOOKAHEAD - 1>();           // stage st arrived (own warp's groups)
        const float* slot = ring + (st % DEPTH) * SLOT_F;
        const int njj = min(2, (N_ - 1) - (tg0 + st * 2));  // exclude current token

        #pragma unroll
        for (int jj = 0; jj < 2; jj++) {
            if (jj < njj) {
                // one K row + one V row, 16B per lane, conflict-free
                const float4 kv = reinterpret_cast<const float4*>(slot + jj * 256)[lid];
                const float4 vv = reinterpret_cast<const float4*>(slot + jj * 256 + 128)[lid];

                float s0 = qr[0][0]*kv.x + qr[0][1]*kv.y + qr[0][2]*kv.z + qr[0][3]*kv.w;
                float s1 = qr[1][0]*kv.x + qr[1][1]*kv.y + qr[1][2]*kv.z + qr[1][3]*kv.w;
                float s2 = qr[2][0]*kv.x + qr[2][1]*kv.y + qr[2][2]*kv.z + qr[2][3]*kv.w;
                float s3 = qr[3][0]*kv.x + qr[3][1]*kv.y + qr[3][2]*kv.z + qr[3][3]*kv.w;

                // butterfly over bits 4,3,2: partial per class (lid&3)
                #pragma unroll
                for (int o = 16; o >= 4; o >>= 1) {
                    s0 += __shfl_xor_sync(0xffffffffu, s0, o);
                    s1 += __shfl_xor_sync(0xffffffffu, s1, o);
                    s2 += __shfl_xor_sync(0xffffffffu, s2, o);
                    s3 += __shfl_xor_sync(0xffffffffu, s3, o);
                }
                // lane picks its group's class-partial, finishes over bits 0,1
                float val = (gsel == 0) ? s0 : (gsel == 1) ? s1 : (gsel == 2) ? s2 : s3;
                val += __shfl_xor_sync(0xffffffffu, val, 1);
                val += __shfl_xor_sync(0xffffffffu, val, 2);
                // val = FULL score for group gsel (uniform in bits 0,1,4)

                const float pv = exp2f(val - C16);      // = e^(s_g - 16)
                l_acc += pv;                            // true l (no cross-lane sum)

                const float p0 = __shfl_sync(0xffffffffu, pv, 0);
                const float p1 = __shfl_sync(0xffffffffu, pv, 4);
                const float p2 = __shfl_sync(0xffffffffu, pv, 8);
                const float p3 = __shfl_sync(0xffffffffu, pv, 12);

                acc[0][0]+=p0*vv.x; acc[0][1]+=p0*vv.y; acc[0][2]+=p0*vv.z; acc[0][3]+=p0*vv.w;
                acc[1][0]+=p1*vv.x; acc[1][1]+=p1*vv.y; acc[1][2]+=p1*vv.z; acc[1][3]+=p1*vv.w;
                acc[2][0]+=p2*vv.x; acc[2][1]+=p2*vv.y; acc[2][2]+=p2*vv.z; acc[2][3]+=p2*vv.w;
                acc[3][0]+=p3*vv.x; acc[3][1]+=p3*vv.y; acc[3][2]+=p3*vv.z; acc[3][3]+=p3*vv.w;
            }
        }

        if (st + LOOKAHEAD < NSTG_rt) issue(st + LOOKAHEAD);  // own-warp refill
        cp_commit();   // possibly-empty group keeps wait counting sound
    }

    cp_wait<0>();
    __syncthreads();

    // CTA-level combine of 8 warp partials (all share M = MFIX -> plain sums)
    float* s_acc = ssm;                 // [WARPS][G_][D_] = 4096 floats
    float* s_l   = ssm + WARPS * G_ * D_;   // [WARPS][G_]

    #pragma unroll
    for (int g = 0; g < G_; g++) {
        float4* dst = reinterpret_cast<float4*>(s_acc + (w * G_ + g) * D_);
        dst[lid] = make_float4(acc[g][0], acc[g][1], acc[g][2], acc[g][3]);
    }
    if (lid < 16 && (lid & 3) == 0)     // lanes 0,4,8,12 hold true l for g=0..3
        s_l[w * G_ + gsel] = l_acc;
    __syncthreads();

    const size_t S = (size_t)p * SLOTS_PP + sp;     // this CTA's scratch slot
    for (int idx = tid; idx < G_ * D_; idx += THREADS) {
        const int gg = idx >> 7;
        const int d  = idx & 127;
        float A = 0.f, L = 0.f;
        #pragma unroll
        for (int ww = 0; ww < WARPS; ww++) {
            A += s_acc[(ww * G_ + gg) * D_ + d];
            L += s_l[ww * G_ + gg];
        }
        g_pacc[(S * G_ + gg) * D_ + d] = A;
        if (d == 0) g_pl[S * G_ + gg] = L;
    }
}

__global__ __launch_bounds__(256)
void attn_combine(const float* __restrict__ Q,
                  const float* __restrict__ K,
                  const float* __restrict__ V,
                  const float* __restrict__ cosp,
                  const float* __restrict__ sinp,
                  float* __restrict__ out)
{
    const int h = blockIdx.x;
    const int b = blockIdx.y;
    const int g  = h >> 3;
    const int kh = h & 7;
    const int tid  = threadIdx.x;
    const int d    = tid & 127;       // output dim
    const int half = tid >> 7;        // slot-half owner

    const int p   = b * HKV_ + kh;
    const int big = (p < A_PAIRS);

    // ---- phase 1 (issued FIRST so loads fly before any barrier): slot sums ----
    float Ls = 0.f, os = 0.f;
    if (big) {
        const size_t base = (size_t)p * SLOTS_PP + half * 4;
        #pragma unroll
        for (int i = 0; i < 4; i++) {
            const size_t S = base + i;
            Ls += g_pl[S * G_ + g];
            os += g_pacc[(S * G_ + g) * D_ + d];
        }
    } else {
        const size_t base = (size_t)p * SLOTS_PP + half * 16;
        #pragma unroll
        for (int i = 0; i < 16; i++) {
            const size_t S = base + i;
            Ls += g_pl[S * G_ + g];
            os += g_pacc[(S * G_ + g) * D_ + d];
        }
    }

    __shared__ float sh_os[2][128];
    __shared__ float sh_Ls[2];
    __shared__ float red[4];

    sh_os[half][d] = os;
    if (d == 0) sh_Ls[half] = Ls;

    // ---- phase 2: current-token score (half 0 threads = warps 0..3) ----
    if (half == 0) {
        const float cv = cosp[(size_t)b * D_ + d];
        const float sv = sinp[(size_t)b * D_ + d];
        const float sign = (d < 64) ? -1.f : 1.f;
        const float* qb = Q + ((size_t)b * H_ + h) * D_;
        const float* kb = K + ((size_t)b * HKV_ + kh) * D_;
        const float qrv = qb[d] * cv + sign * qb[d ^ 64] * sv;
        const float krv = kb[d] * cv + sign * kb[d ^ 64] * sv;
        float part = qrv * krv;
        #pragma unroll
        for (int o = 16; o; o >>= 1) part += __shfl_xor_sync(0xffffffffu, part, o);
        if ((d & 31) == 0) red[d >> 5] = part;
    }
    __syncthreads();

    if (half == 0) {
        const float s_cur = (red[0] + red[1] + red[2] + red[3]) * SCALE_;
        const float M  = fmaxf(s_cur, MFIX);      // all split partials share M = MFIX
        const float ec = __expf(s_cur - M);
        const float cf = __expf(MFIX - M);
        const float L  = ec + (sh_Ls[0] + sh_Ls[1]) * cf;
        const float o_ = ec * V[((size_t)b * HKV_ + kh) * D_ + d]
                       + (sh_os[0][d] + sh_os[1][d]) * cf;
        out[((size_t)b * H_ + h) * D_ + d] = o_ / L;
    }
}

extern "C" void kernel_launch(void* const* d_in, const int* in_sizes, int n_in,
                              void* d_out, int out_size)
{
    const float* Q    = (const float*)d_in[0];
    const float* K    = (const float*)d_in[1];
    const float* V    = (const float*)d_in[2];
    const float* Kc   = (const float*)d_in[3];
    const float* Vc   = (const float*)d_in[4];
    const float* cosp = (const float*)d_in[5];
    const float* sinp = (const float*)d_in[6];
    const int*   bt   = (const int*)d_in[7];
    float* out = (float*)d_out;

    attn_main<<<GRID_MAIN, THREADS>>>(Q, Kc, Vc, cosp, sinp, bt);

    dim3 grid_comb(H_, B_);
    attn_combine<<<grid_comb, 256>>>(Q, K, V, cosp, sinp, out);
}

// round 16
// speedup vs baseline: 1.0419x; 1.0164x over previous
#include <cuda_runtime.h>
#include <cstdint>
#include <math.h>

#define DEV_INLINE __device__ __forceinline__

constexpr int B_   = 32;
constexpr int H_   = 32;
constexpr int HKV_ = 8;
constexpr int D_   = 128;
constexpr int G_   = 4;      // H_/HKV_
constexpr int N_   = 4096;
constexpr int NB_  = 256;    // 16-token paged blocks per sequence
constexpr int WARPS = 8;
constexpr int THREADS = 256;
constexpr int DEPTH = 4;            // warp-private ring slots (64 KB total)
constexpr int LOOKAHEAD = 3;        // stages in flight per warp
constexpr int SLOT_F = 512;         // floats per slot: 2 tok x (128 K + 128 V)

// Two-class decomposition (R12 geometry — best measured for main):
// 222 pairs x 8 big splits (32 blocks) = 1776 CTAs, then 34 pairs x 32 small
// splits (8 blocks) = 1088 short CTAs that let work-stealing pack the drain.
constexpr int A_PAIRS = 222;
constexpr int A_JOBS  = A_PAIRS * 8;          // 1776
constexpr int GRID_MAIN = A_JOBS + (B_ * HKV_ - A_PAIRS) * 32;  // 1776 + 1088 = 2864
constexpr int SLOTS_PP = 32;                  // scratch slots per pair (A uses 8)

constexpr float SCALE_ = 0.08838834764831845f;
constexpr float LOG2E  = 1.4426950408889634f;
constexpr float SCALE_L2E = SCALE_ * LOG2E;   // qr prescale (exp2 domain)
constexpr float MFIX   = 16.0f;               // fixed softmax max
constexpr float C16    = MFIX * LOG2E;        // subtract in exp2 domain

// Partial scratch (allocation-free __device__ globals)
// layout: [pair][slot][g][d] and [pair][slot][g]
__device__ float g_pacc[(size_t)B_ * HKV_ * SLOTS_PP * G_ * D_];   // 16.8 MB
__device__ float g_pl[(size_t)B_ * HKV_ * SLOTS_PP * G_];

DEV_INLINE void cp_async16(unsigned int smem_addr, const void* gptr) {
    asm volatile("cp.async.cg.shared.global [%0], [%1], 16;\n"
                 :: "r"(smem_addr), "l"(gptr));
}
DEV_INLINE void cp_commit() { asm volatile("cp.async.commit_group;\n"); }
template <int NN> DEV_INLINE void cp_wait() {
    asm volatile("cp.async.wait_group %0;\n" :: "n"(NN));
}
DEV_INLINE void griddep_launch_dependents() {
    asm volatile("griddepcontrol.launch_dependents;");
}
DEV_INLINE void griddep_wait() {
    asm volatile("griddepcontrol.wait;");
}

__global__ __launch_bounds__(THREADS, 3)
void attn_main(const float* __restrict__ Q,
               const float* __restrict__ Kc,
               const float* __restrict__ Vc,
               const float* __restrict__ cosp,
               const float* __restrict__ sinp,
               const int* __restrict__ bt)
{
    const int c   = blockIdx.x;
    const int tid = threadIdx.x;
    const int w   = tid >> 5;
    const int lid = tid & 31;
    const int gsel = (lid >> 2) & 3;    // group this lane finishes in the reduction

    // decode two-class work assignment
    int p, sp, nbw;          // pair, split, blocks-per-warp
    if (c < A_JOBS) { p = c >> 3;               sp = c & 7;  nbw = 4; }
    else            { const int cc = c - A_JOBS; p = A_PAIRS + (cc >> 5); sp = cc & 31; nbw = 1; }
    const int b  = p >> 3;
    const int kh = p & 7;
    const int block0_w = (nbw == 4) ? (sp * 32 + w * 4) : (sp * 8 + w);
    const int NSTG_rt  = nbw * 8;       // stages of 2 tokens: 32 (A) or 8 (B)

    // 64 KB static: 8 warp-private rings of DEPTH x SLOT_F floats
    __shared__ __align__(16) float ssm[WARPS * DEPTH * SLOT_F];
    float* ring = ssm + w * (DEPTH * SLOT_F);

    // Lane owns d-chunk: d = lid*4 + j (full-warp spread -> 2 LDS/token)
    float qr[G_][4];
    {
        const float* cb = cosp + (size_t)b * D_;
        const float* sb = sinp + (size_t)b * D_;
        #pragma unroll
        for (int g = 0; g < G_; g++) {
            const float* qb = Q + ((size_t)b * H_ + g * HKV_ + kh) * D_;
            #pragma unroll
            for (int j = 0; j < 4; j++) {
                const int d = lid * 4 + j;
                const float sign = (d < 64) ? -1.f : 1.f;
                qr[g][j] = (qb[d] * cb[d] + sign * qb[d ^ 64] * sb[d]) * SCALE_L2E;
            }
        }
    }

    // paged-block offsets for this warp (guard OOB for class B)
    const int* btb = bt + (size_t)b * NB_ + block0_w;
    size_t boff[4];
    #pragma unroll
    for (int i = 0; i < 4; i++) {
        const int idx = (i < nbw) ? i : 0;
        boff[i] = (size_t)__ldg(btb + idx) * 16384 + (size_t)kh * 2048;
    }

    auto issue = [&](int st) {
        const size_t o = boff[st >> 3] + (size_t)((st * 2) & 15) * 128;
        const float* gK = Kc + o;
        const float* gV = Vc + o;
        unsigned int s = (unsigned int)__cvta_generic_to_shared(ring + (st % DEPTH) * SLOT_F);
        cp_async16(s +    0 + lid * 16, gK + lid * 4);
        cp_async16(s +  512 + lid * 16, gV + lid * 4);
        cp_async16(s + 1024 + lid * 16, gK + 128 + lid * 4);
        cp_async16(s + 1536 + lid * 16, gV + 128 + lid * 4);
    };

    #pragma unroll
    for (int s = 0; s < LOOKAHEAD; s++) { issue(s); cp_commit(); }

    float l_acc = 0.f;             // per-lane: TRUE l for group gsel
    float acc[G_][4];
    #pragma unroll
    for (int g = 0; g < G_; g++)
        #pragma unroll
        for (int j = 0; j < 4; j++) acc[g][j] = 0.f;

    const int tg0 = block0_w * 16;  // global token index of warp's first token

    for (int st = 0; st < NSTG_rt; st++) {
        cp_wait<LOOKAHEAD - 1>();           // stage st arrived (own warp's groups)
        const float* slot = ring + (st % DEPTH) * SLOT_F;
        const int njj = min(2, (N_ - 1) - (tg0 + st * 2));  // exclude current token

        #pragma unroll
        for (int jj = 0; jj < 2; jj++) {
            if (jj < njj) {
                // one K row + one V row, 16B per lane, conflict-free
                const float4 kv = reinterpret_cast<const float4*>(slot + jj * 256)[lid];
                const float4 vv = reinterpret_cast<const float4*>(slot + jj * 256 + 128)[lid];

                float s0 = qr[0][0]*kv.x + qr[0][1]*kv.y + qr[0][2]*kv.z + qr[0][3]*kv.w;
                float s1 = qr[1][0]*kv.x + qr[1][1]*kv.y + qr[1][2]*kv.z + qr[1][3]*kv.w;
                float s2 = qr[2][0]*kv.x + qr[2][1]*kv.y + qr[2][2]*kv.z + qr[2][3]*kv.w;
                float s3 = qr[3][0]*kv.x + qr[3][1]*kv.y + qr[3][2]*kv.z + qr[3][3]*kv.w;

                // butterfly over bits 4,3,2: partial per class (lid&3)
                #pragma unroll
                for (int o = 16; o >= 4; o >>= 1) {
                    s0 += __shfl_xor_sync(0xffffffffu, s0, o);
                    s1 += __shfl_xor_sync(0xffffffffu, s1, o);
                    s2 += __shfl_xor_sync(0xffffffffu, s2, o);
                    s3 += __shfl_xor_sync(0xffffffffu, s3, o);
                }
                // lane picks its group's class-partial, finishes over bits 0,1
                float val = (gsel == 0) ? s0 : (gsel == 1) ? s1 : (gsel == 2) ? s2 : s3;
                val += __shfl_xor_sync(0xffffffffu, val, 1);
                val += __shfl_xor_sync(0xffffffffu, val, 2);
                // val = FULL score for group gsel (uniform in bits 0,1,4)

                const float pv = exp2f(val - C16);      // = e^(s_g - 16)
                l_acc += pv;                            // true l (no cross-lane sum)

                const float p0 = __shfl_sync(0xffffffffu, pv, 0);
                const float p1 = __shfl_sync(0xffffffffu, pv, 4);
                const float p2 = __shfl_sync(0xffffffffu, pv, 8);
                const float p3 = __shfl_sync(0xffffffffu, pv, 12);

                acc[0][0]+=p0*vv.x; acc[0][1]+=p0*vv.y; acc[0][2]+=p0*vv.z; acc[0][3]+=p0*vv.w;
                acc[1][0]+=p1*vv.x; acc[1][1]+=p1*vv.y; acc[1][2]+=p1*vv.z; acc[1][3]+=p1*vv.w;
                acc[2][0]+=p2*vv.x; acc[2][1]+=p2*vv.y; acc[2][2]+=p2*vv.z; acc[2][3]+=p2*vv.w;
                acc[3][0]+=p3*vv.x; acc[3][1]+=p3*vv.y; acc[3][2]+=p3*vv.z; acc[3][3]+=p3*vv.w;
            }
        }

        if (st + LOOKAHEAD < NSTG_rt) issue(st + LOOKAHEAD);  // own-warp refill
        cp_commit();   // possibly-empty group keeps wait counting sound
    }

    cp_wait<0>();
    // KV streaming done for this CTA — let combine CTAs start launching/prologue.
    griddep_launch_dependents();
    __syncthreads();

    // CTA-level combine of 8 warp partials (all share M = MFIX -> plain sums)
    float* s_acc = ssm;                 // [WARPS][G_][D_] = 4096 floats
    float* s_l   = ssm + WARPS * G_ * D_;   // [WARPS][G_]

    #pragma unroll
    for (int g = 0; g < G_; g++) {
        float4* dst = reinterpret_cast<float4*>(s_acc + (w * G_ + g) * D_);
        dst[lid] = make_float4(acc[g][0], acc[g][1], acc[g][2], acc[g][3]);
    }
    if (lid < 16 && (lid & 3) == 0)     // lanes 0,4,8,12 hold true l for g=0..3
        s_l[w * G_ + gsel] = l_acc;
    __syncthreads();

    const size_t S = (size_t)p * SLOTS_PP + sp;     // this CTA's scratch slot
    for (int idx = tid; idx < G_ * D_; idx += THREADS) {
        const int gg = idx >> 7;
        const int d  = idx & 127;
        float A = 0.f, L = 0.f;
        #pragma unroll
        for (int ww = 0; ww < WARPS; ww++) {
            A += s_acc[(ww * G_ + gg) * D_ + d];
            L += s_l[ww * G_ + gg];
        }
        g_pacc[(S * G_ + gg) * D_ + d] = A;
        if (d == 0) g_pl[S * G_ + gg] = L;
    }
}

__global__ __launch_bounds__(256)
void attn_combine(const float* __restrict__ Q,
                  const float* __restrict__ K,
                  const float* __restrict__ V,
                  const float* __restrict__ cosp,
                  const float* __restrict__ sinp,
                  float* __restrict__ out)
{
    const int h = blockIdx.x;
    const int b = blockIdx.y;
    const int g  = h >> 3;
    const int kh = h & 7;
    const int tid  = threadIdx.x;
    const int d    = tid & 127;       // output dim
    const int half = tid >> 7;        // slot-half owner

    const int p   = b * HKV_ + kh;
    const int big = (p < A_PAIRS);

    // ---- PDL prologue: input-only work, overlaps main's drain ----
    float part = 0.f, vval = 0.f;
    if (half == 0) {
        const float cv = cosp[(size_t)b * D_ + d];
        const float sv = sinp[(size_t)b * D_ + d];
        const float sign = (d < 64) ? -1.f : 1.f;
        const float* qb = Q + ((size_t)b * H_ + h) * D_;
        const float* kb = K + ((size_t)b * HKV_ + kh) * D_;
        const float qrv = qb[d] * cv + sign * qb[d ^ 64] * sv;
        const float krv = kb[d] * cv + sign * kb[d ^ 64] * sv;
        part = qrv * krv;
        vval = V[((size_t)b * HKV_ + kh) * D_ + d];
    }

    // ---- wait for main's scratch to be visible ----
    griddep_wait();

    // ---- slot sums (loads issued before any barrier) ----
    float Ls = 0.f, os = 0.f;
    if (big) {
        const size_t base = (size_t)p * SLOTS_PP + half * 4;
        #pragma unroll
        for (int i = 0; i < 4; i++) {
            const size_t S = base + i;
            Ls += g_pl[S * G_ + g];
            os += g_pacc[(S * G_ + g) * D_ + d];
        }
    } else {
        const size_t base = (size_t)p * SLOTS_PP + half * 16;
        #pragma unroll
        for (int i = 0; i < 16; i++) {
            const size_t S = base + i;
            Ls += g_pl[S * G_ + g];
            os += g_pacc[(S * G_ + g) * D_ + d];
        }
    }

    __shared__ float sh_os[2][128];
    __shared__ float sh_Ls[2];
    __shared__ float red[4];

    sh_os[half][d] = os;
    if (d == 0) sh_Ls[half] = Ls;

    if (half == 0) {
        #pragma unroll
        for (int o = 16; o; o >>= 1) part += __shfl_xor_sync(0xffffffffu, part, o);
        if ((d & 31) == 0) red[d >> 5] = part;
    }
    __syncthreads();

    if (half == 0) {
        const float s_cur = (red[0] + red[1] + red[2] + red[3]) * SCALE_;
        const float M  = fmaxf(s_cur, MFIX);      // all split partials share M = MFIX
        const float ec = __expf(s_cur - M);
        const float cf = __expf(MFIX - M);
        const float L  = ec + (sh_Ls[0] + sh_Ls[1]) * cf;
        const float o_ = ec * vval + (sh_os[0][d] + sh_os[1][d]) * cf;
        out[((size_t)b * H_ + h) * D_ + d] = o_ / L;
    }
}

extern "C" void kernel_launch(void* const* d_in, const int* in_sizes, int n_in,
                              void* d_out, int out_size)
{
    const float* Q    = (const float*)d_in[0];
    const float* K    = (const float*)d_in[1];
    const float* V    = (const float*)d_in[2];
    const float* Kc   = (const float*)d_in[3];
    const float* Vc   = (const float*)d_in[4];
    const float* cosp = (const float*)d_in[5];
    const float* sinp = (const float*)d_in[6];
    const int*   bt   = (const int*)d_in[7];
    float* out = (float*)d_out;

    attn_main<<<GRID_MAIN, THREADS>>>(Q, Kc, Vc, cosp, sinp, bt);

    // combine with programmatic dependent launch (overlaps main's drain)
    cudaLaunchConfig_t cfg = {};
    cfg.gridDim  = dim3(H_, B_, 1);
    cfg.blockDim = dim3(256, 1, 1);
    cfg.dynamicSmemBytes = 0;
    cfg.stream = 0;   // same (legacy default) stream as <<<>>>
    cudaLaunchAttribute attrs[1];
    attrs[0].id = cudaLaunchAttributeProgrammaticStreamSerialization;
    attrs[0].val.programmaticStreamSerializationAllowed = 1;
    cfg.attrs = attrs;
    cfg.numAttrs = 1;
    cudaLaunchKernelEx(&cfg, attn_combine, Q, K, V, cosp, sinp, out);
}

// round 17
// speedup vs baseline: 1.1148x; 1.0700x over previous
#include <cuda_runtime.h>
#include <cstdint>
#include <math.h>

#define DEV_INLINE __device__ __forceinline__

constexpr int B_   = 32;
constexpr int H_   = 32;
constexpr int HKV_ = 8;
constexpr int D_   = 128;
constexpr int G_   = 4;      // H_/HKV_
constexpr int N_   = 4096;
constexpr int NB_  = 256;    // 16-token paged blocks per sequence
constexpr int WARPS = 8;
constexpr int THREADS = 256;
constexpr int DEPTH = 4;            // warp-private ring slots (64 KB total)
constexpr int LOOKAHEAD = 3;        // stages in flight per warp
constexpr int SLOT_F = 512;         // floats per slot: 2 tok x (128 K + 128 V)

// Two-class decomposition:
// class A: 222 pairs x 4 big splits (64 blocks/CTA) = 888 CTAs = exactly 2 full
//          waves at occ 3 (444 concurrent CTAs).
// class B: 34 pairs x 32 small splits (8 blocks/CTA) = 1088 short CTAs that let
//          work-stealing pack the drain (R12-proven pool size).
constexpr int A_PAIRS = 222;
constexpr int A_JOBS  = A_PAIRS * 4;          // 888
constexpr int GRID_MAIN = A_JOBS + (B_ * HKV_ - A_PAIRS) * 32;  // 888 + 1088 = 1976
constexpr int SLOTS_PP = 32;                  // scratch slots per pair (A uses 4)

constexpr float SCALE_ = 0.08838834764831845f;
constexpr float LOG2E  = 1.4426950408889634f;
constexpr float SCALE_L2E = SCALE_ * LOG2E;   // qr prescale (exp2 domain)
constexpr float MFIX   = 16.0f;               // fixed softmax max
constexpr float C16    = MFIX * LOG2E;        // subtract in exp2 domain

// Partial scratch (allocation-free __device__ globals)
// layout: [pair][slot][g][d] and [pair][slot][g]
__device__ float g_pacc[(size_t)B_ * HKV_ * SLOTS_PP * G_ * D_];   // 16.8 MB
__device__ float g_pl[(size_t)B_ * HKV_ * SLOTS_PP * G_];

DEV_INLINE void cp_async16(unsigned int smem_addr, const void* gptr) {
    asm volatile("cp.async.cg.shared.global [%0], [%1], 16;\n"
                 :: "r"(smem_addr), "l"(gptr));
}
DEV_INLINE void cp_commit() { asm volatile("cp.async.commit_group;\n"); }
template <int NN> DEV_INLINE void cp_wait() {
    asm volatile("cp.async.wait_group %0;\n" :: "n"(NN));
}
DEV_INLINE void griddep_launch_dependents() {
    asm volatile("griddepcontrol.launch_dependents;");
}
DEV_INLINE void griddep_wait() {
    asm volatile("griddepcontrol.wait;");
}

__global__ __launch_bounds__(THREADS, 3)
void attn_main(const float* __restrict__ Q,
               const float* __restrict__ Kc,
               const float* __restrict__ Vc,
               const float* __restrict__ cosp,
               const float* __restrict__ sinp,
               const int* __restrict__ bt)
{
    const int c   = blockIdx.x;
    const int tid = threadIdx.x;
    const int w   = tid >> 5;
    const int lid = tid & 31;
    const int gsel = (lid >> 2) & 3;    // group this lane finishes in the reduction

    // decode two-class work assignment
    int p, sp, nbw;          // pair, split, blocks-per-warp
    if (c < A_JOBS) { p = c >> 2;               sp = c & 3;  nbw = 8; }
    else            { const int cc = c - A_JOBS; p = A_PAIRS + (cc >> 5); sp = cc & 31; nbw = 1; }
    const int b  = p >> 3;
    const int kh = p & 7;
    const int block0_w = (nbw == 8) ? (sp * 64 + w * 8) : (sp * 8 + w);
    const int NSTG_rt  = nbw * 8;       // stages of 2 tokens: 64 (A) or 8 (B)

    // 64 KB ring + 512 B block-offset table
    __shared__ __align__(16) float ssm[WARPS * DEPTH * SLOT_F];
    __shared__ size_t sboff[WARPS][8];
    float* ring = ssm + w * (DEPTH * SLOT_F);

    // per-warp block offsets into smem (frees registers for the 8-block case)
    {
        const int* btb = bt + (size_t)b * NB_ + block0_w;
        if (lid < 8) {
            const int idx = (lid < nbw) ? lid : 0;
            sboff[w][lid] = (size_t)__ldg(btb + idx) * 16384 + (size_t)kh * 2048;
        }
        __syncwarp();
    }

    // Lane owns d-chunk: d = lid*4 + j (full-warp spread -> 2 LDS/token)
    float qr[G_][4];
    {
        const float* cb = cosp + (size_t)b * D_;
        const float* sb = sinp + (size_t)b * D_;
        #pragma unroll
        for (int g = 0; g < G_; g++) {
            const float* qb = Q + ((size_t)b * H_ + g * HKV_ + kh) * D_;
            #pragma unroll
            for (int j = 0; j < 4; j++) {
                const int d = lid * 4 + j;
                const float sign = (d < 64) ? -1.f : 1.f;
                qr[g][j] = (qb[d] * cb[d] + sign * qb[d ^ 64] * sb[d]) * SCALE_L2E;
            }
        }
    }

    auto issue = [&](int st) {
        const size_t o = sboff[w][st >> 3] + (size_t)((st * 2) & 15) * 128;
        const float* gK = Kc + o;
        const float* gV = Vc + o;
        unsigned int s = (unsigned int)__cvta_generic_to_shared(ring + (st % DEPTH) * SLOT_F);
        cp_async16(s +    0 + lid * 16, gK + lid * 4);
        cp_async16(s +  512 + lid * 16, gV + lid * 4);
        cp_async16(s + 1024 + lid * 16, gK + 128 + lid * 4);
        cp_async16(s + 1536 + lid * 16, gV + 128 + lid * 4);
    };

    #pragma unroll
    for (int s = 0; s < LOOKAHEAD; s++) { issue(s); cp_commit(); }

    float l_acc = 0.f;             // per-lane: TRUE l for group gsel
    float acc[G_][4];
    #pragma unroll
    for (int g = 0; g < G_; g++)
        #pragma unroll
        for (int j = 0; j < 4; j++) acc[g][j] = 0.f;

    const int tg0 = block0_w * 16;  // global token index of warp's first token

    for (int st = 0; st < NSTG_rt; st++) {
        cp_wait<LOOKAHEAD - 1>();           // stage st arrived (own warp's groups)
        const float* slot = ring + (st % DEPTH) * SLOT_F;
        const int njj = min(2, (N_ - 1) - (tg0 + st * 2));  // exclude current token

        #pragma unroll
        for (int jj = 0; jj < 2; jj++) {
            if (jj < njj) {
                // one K row + one V row, 16B per lane, conflict-free
                const float4 kv = reinterpret_cast<const float4*>(slot + jj * 256)[lid];
                const float4 vv = reinterpret_cast<const float4*>(slot + jj * 256 + 128)[lid];

                float s0 = qr[0][0]*kv.x + qr[0][1]*kv.y + qr[0][2]*kv.z + qr[0][3]*kv.w;
                float s1 = qr[1][0]*kv.x + qr[1][1]*kv.y + qr[1][2]*kv.z + qr[1][3]*kv.w;
                float s2 = qr[2][0]*kv.x + qr[2][1]*kv.y + qr[2][2]*kv.z + qr[2][3]*kv.w;
                float s3 = qr[3][0]*kv.x + qr[3][1]*kv.y + qr[3][2]*kv.z + qr[3][3]*kv.w;

                // butterfly over bits 4,3,2: partial per class (lid&3)
                #pragma unroll
                for (int o = 16; o >= 4; o >>= 1) {
                    s0 += __shfl_xor_sync(0xffffffffu, s0, o);
                    s1 += __shfl_xor_sync(0xffffffffu, s1, o);
                    s2 += __shfl_xor_sync(0xffffffffu, s2, o);
                    s3 += __shfl_xor_sync(0xffffffffu, s3, o);
                }
                // lane picks its group's class-partial, finishes over bits 0,1
                float val = (gsel == 0) ? s0 : (gsel == 1) ? s1 : (gsel == 2) ? s2 : s3;
                val += __shfl_xor_sync(0xffffffffu, val, 1);
                val += __shfl_xor_sync(0xffffffffu, val, 2);
                // val = FULL score for group gsel (uniform in bits 0,1,4)

                const float pv = exp2f(val - C16);      // = e^(s_g - 16)
                l_acc += pv;                            // true l (no cross-lane sum)

                const float p0 = __shfl_sync(0xffffffffu, pv, 0);
                const float p1 = __shfl_sync(0xffffffffu, pv, 4);
                const float p2 = __shfl_sync(0xffffffffu, pv, 8);
                const float p3 = __shfl_sync(0xffffffffu, pv, 12);

                acc[0][0]+=p0*vv.x; acc[0][1]+=p0*vv.y; acc[0][2]+=p0*vv.z; acc[0][3]+=p0*vv.w;
                acc[1][0]+=p1*vv.x; acc[1][1]+=p1*vv.y; acc[1][2]+=p1*vv.z; acc[1][3]+=p1*vv.w;
                acc[2][0]+=p2*vv.x; acc[2][1]+=p2*vv.y; acc[2][2]+=p2*vv.z; acc[2][3]+=p2*vv.w;
                acc[3][0]+=p3*vv.x; acc[3][1]+=p3*vv.y; acc[3][2]+=p3*vv.z; acc[3][3]+=p3*vv.w;
            }
        }

        if (st + LOOKAHEAD < NSTG_rt) issue(st + LOOKAHEAD);  // own-warp refill
        cp_commit();   // possibly-empty group keeps wait counting sound
    }

    cp_wait<0>();
    // KV streaming done for this CTA — let combine CTAs start launching/prologue.
    griddep_launch_dependents();
    __syncthreads();

    // CTA-level combine of 8 warp partials (all share M = MFIX -> plain sums)
    float* s_acc = ssm;                 // [WARPS][G_][D_] = 4096 floats
    float* s_l   = ssm + WARPS * G_ * D_;   // [WARPS][G_]

    #pragma unroll
    for (int g = 0; g < G_; g++) {
        float4* dst = reinterpret_cast<float4*>(s_acc + (w * G_ + g) * D_);
        dst[lid] = make_float4(acc[g][0], acc[g][1], acc[g][2], acc[g][3]);
    }
    if (lid < 16 && (lid & 3) == 0)     // lanes 0,4,8,12 hold true l for g=0..3
        s_l[w * G_ + gsel] = l_acc;
    __syncthreads();

    const size_t S = (size_t)p * SLOTS_PP + sp;     // this CTA's scratch slot
    for (int idx = tid; idx < G_ * D_; idx += THREADS) {
        const int gg = idx >> 7;
        const int d  = idx & 127;
        float A = 0.f, L = 0.f;
        #pragma unroll
        for (int ww = 0; ww < WARPS; ww++) {
            A += s_acc[(ww * G_ + gg) * D_ + d];
            L += s_l[ww * G_ + gg];
        }
        g_pacc[(S * G_ + gg) * D_ + d] = A;
        if (d == 0) g_pl[S * G_ + gg] = L;
    }
}

__global__ __launch_bounds__(256)
void attn_combine(const float* __restrict__ Q,
                  const float* __restrict__ K,
                  const float* __restrict__ V,
                  const float* __restrict__ cosp,
                  const float* __restrict__ sinp,
                  float* __restrict__ out)
{
    const int h = blockIdx.x;
    const int b = blockIdx.y;
    const int g  = h >> 3;
    const int kh = h & 7;
    const int tid  = threadIdx.x;
    const int d    = tid & 127;       // output dim
    const int half = tid >> 7;        // slot-half owner

    const int p   = b * HKV_ + kh;
    const int big = (p < A_PAIRS);

    // ---- PDL prologue: input-only work, overlaps main's drain ----
    float part = 0.f, vval = 0.f;
    if (half == 0) {
        const float cv = cosp[(size_t)b * D_ + d];
        const float sv = sinp[(size_t)b * D_ + d];
        const float sign = (d < 64) ? -1.f : 1.f;
        const float* qb = Q + ((size_t)b * H_ + h) * D_;
        const float* kb = K + ((size_t)b * HKV_ + kh) * D_;
        const float qrv = qb[d] * cv + sign * qb[d ^ 64] * sv;
        const float krv = kb[d] * cv + sign * kb[d ^ 64] * sv;
        part = qrv * krv;
        vval = V[((size_t)b * HKV_ + kh) * D_ + d];
    }

    // ---- wait for main's scratch to be visible ----
    griddep_wait();

    // ---- slot sums (loads issued before any barrier) ----
    float Ls = 0.f, os = 0.f;
    if (big) {
        const size_t base = (size_t)p * SLOTS_PP + half * 2;   // A uses 4 slots
        #pragma unroll
        for (int i = 0; i < 2; i++) {
            const size_t S = base + i;
            Ls += g_pl[S * G_ + g];
            os += g_pacc[(S * G_ + g) * D_ + d];
        }
    } else {
        const size_t base = (size_t)p * SLOTS_PP + half * 16;
        #pragma unroll
        for (int i = 0; i < 16; i++) {
            const size_t S = base + i;
            Ls += g_pl[S * G_ + g];
            os += g_pacc[(S * G_ + g) * D_ + d];
        }
    }

    __shared__ float sh_os[2][128];
    __shared__ float sh_Ls[2];
    __shared__ float red[4];

    sh_os[half][d] = os;
    if (d == 0) sh_Ls[half] = Ls;

    if (half == 0) {
        #pragma unroll
        for (int o = 16; o; o >>= 1) part += __shfl_xor_sync(0xffffffffu, part, o);
        if ((d & 31) == 0) red[d >> 5] = part;
    }
    __syncthreads();

    if (half == 0) {
        const float s_cur = (red[0] + red[1] + red[2] + red[3]) * SCALE_;
        const float M  = fmaxf(s_cur, MFIX);      // all split partials share M = MFIX
        const float ec = __expf(s_cur - M);
        const float cf = __expf(MFIX - M);
        const float L  = ec + (sh_Ls[0] + sh_Ls[1]) * cf;
        const float o_ = ec * vval + (sh_os[0][d] + sh_os[1][d]) * cf;
        out[((size_t)b * H_ + h) * D_ + d] = o_ / L;
    }
}

extern "C" void kernel_launch(void* const* d_in, const int* in_sizes, int n_in,
                              void* d_out, int out_size)
{
    const float* Q    = (const float*)d_in[0];
    const float* K    = (const float*)d_in[1];
    const float* V    = (const float*)d_in[2];
    const float* Kc   = (const float*)d_in[3];
    const float* Vc   = (const float*)d_in[4];
    const float* cosp = (const float*)d_in[5];
    const float* sinp = (const float*)d_in[6];
    const int*   bt   = (const int*)d_in[7];
    float* out = (float*)d_out;

    attn_main<<<GRID_MAIN, THREADS>>>(Q, Kc, Vc, cosp, sinp, bt);

    // combine with programmatic dependent launch (overlaps main's drain)
    cudaLaunchConfig_t cfg = {};
    cfg.gridDim  = dim3(H_, B_, 1);
    cfg.blockDim = dim3(256, 1, 1);
    cfg.dynamicSmemBytes = 0;
    cfg.stream = 0;   // same (legacy default) stream as <<<>>>
    cudaLaunchAttribute attrs[1];
    attrs[0].id = cudaLaunchAttributeProgrammaticStreamSerialization;
    attrs[0].val.programmaticStreamSerializationAllowed = 1;
    cfg.attrs = attrs;
    cfg.numAttrs = 1;
    cudaLaunchKernelEx(&cfg, attn_combine, Q, K, V, cosp, sinp, out);
}